// round 2
// baseline (speedup 1.0000x reference)
#include <cuda_runtime.h>
#include <cstdint>
#include <cstddef>

#define N_NODES 50000
#define N_EDGES 640000
#define DDIM 128

// smem row strides (floats), padded to dodge bank conflicts, 16B-aligned rows
#define AS_STRIDE 388   // edge A tile: 384 + 4
#define NS_STRIDE 260   // node A tile: 256 + 4
#define HS_STRIDE 132   // hidden tile: 128 + 4

static const int SMEM_EDGE = (64 * AS_STRIDE + 64 * DDIM) * 4;  // 132096 B
static const int SMEM_NODE = (64 * NS_STRIDE + 64 * DDIM) * 4;  //  99328 B

// Scratch (no runtime allocation allowed): scatter-sum accumulator + counts
__device__ float g_agg[(size_t)N_NODES * DDIM];
__device__ float g_cnt[N_NODES];

// Blackwell packed fp32 pipe: 2 exact fp32 FMAs per instruction (PTX-only form)
#define FMA2(d, a, b, c) \
    asm("fma.rn.f32x2 %0, %1, %2, %3;" : "=l"(d) : "l"(a), "l"(b), "l"(c))
#define PACK_AA(d, a) \
    asm("mov.b64 %0, {%1, %1};" : "=l"(d) : "f"(a))
#define UNPACK2(lo, hi, v) \
    asm("mov.b64 {%0, %1}, %2;" : "=f"(lo), "=f"(hi) : "l"(v))

__device__ __forceinline__ int clamp_node(int v) {
    return v < 0 ? 0 : (v >= N_NODES ? N_NODES - 1 : v);
}

__global__ void zero_kernel() {
    const size_t stride = (size_t)gridDim.x * blockDim.x;
    for (size_t i = (size_t)blockIdx.x * blockDim.x + threadIdx.x;
         i < (size_t)N_NODES * DDIM; i += stride)
        g_agg[i] = 0.0f;
    for (int i = blockIdx.x * blockDim.x + threadIdx.x; i < N_NODES;
         i += (int)stride)
        g_cnt[i] = 0.0f;
}

// ---------------------------------------------------------------------------
// Edge kernel: per CTA, 64 edges x 128 outputs.
//   A = [x[row] | x[col] | edge_attr]  (gathered to smem, [64][388])
//   H = relu(A @ We1 + be1)            (reg accum -> smem, [64][132])
//   O = H @ We2 + be2                  -> edge_out, + atomic scatter to g_agg
// Threads: 256 as 16x16; each thread owns 4 rows x 8 cols (4 f32x2 pairs).
// ---------------------------------------------------------------------------
__global__ __launch_bounds__(256, 1)
void edge_kernel(const float* __restrict__ x,
                 const int* __restrict__ ei,          // int32 (jax x64 disabled)
                 const float* __restrict__ ea,
                 const float* __restrict__ We1,
                 const float* __restrict__ be1,
                 const float* __restrict__ We2,
                 const float* __restrict__ be2,
                 float* __restrict__ edge_out)
{
    extern __shared__ float sm[];
    float* Asm = sm;                          // [64][AS_STRIDE]
    float* Wsm = sm + 64 * AS_STRIDE;         // [64][128] weight K-chunk
    float* Hsm = sm;                          // aliases Asm after GEMM1

    __shared__ int srow[64];
    __shared__ int scol[64];

    const int tid    = threadIdx.x;
    const int e_base = blockIdx.x * 64;

    if (tid < 64) {
        srow[tid] = clamp_node(ei[e_base + tid]);
        scol[tid] = clamp_node(ei[N_EDGES + e_base + tid]);
    }
    __syncthreads();

    // Gather A: 192 (edge,segment) rows of 128 floats; one warp per row.
    {
        const int warp = tid >> 5, lane = tid & 31;
        for (int rr = warp; rr < 192; rr += 8) {
            const int e   = rr & 63;
            const int seg = rr >> 6;
            const float* src;
            if (seg == 0)      src = x  + (size_t)srow[e] * DDIM;
            else if (seg == 1) src = x  + (size_t)scol[e] * DDIM;
            else               src = ea + (size_t)(e_base + e) * DDIM;
            const float4 v = reinterpret_cast<const float4*>(src)[lane];
            reinterpret_cast<float4*>(&Asm[e * AS_STRIDE + seg * DDIM])[lane] = v;
        }
    }
    __syncthreads();

    const int tx = tid & 15, ty = tid >> 4;
    const int c0 = tx * 8;   // 8 output cols = 4 f32x2 pairs
    const int r0 = ty * 4;   // 4 rows

    unsigned long long acc[4][4];
    {
        const unsigned long long* bb =
            reinterpret_cast<const unsigned long long*>(be1 + c0);
        const unsigned long long b0 = bb[0], b1 = bb[1], b2 = bb[2], b3 = bb[3];
        #pragma unroll
        for (int i = 0; i < 4; ++i) {
            acc[i][0] = b0; acc[i][1] = b1; acc[i][2] = b2; acc[i][3] = b3;
        }
    }

    // ---- GEMM1: K = 384, chunks of 64 ----
    for (int kc = 0; kc < 384; kc += 64) {
        for (int i = tid; i < 64 * DDIM / 4; i += 256)
            reinterpret_cast<float4*>(Wsm)[i] =
                reinterpret_cast<const float4*>(We1 + (size_t)kc * DDIM)[i];
        __syncthreads();
        #pragma unroll 16
        for (int k = 0; k < 64; ++k) {
            const unsigned long long* bp =
                reinterpret_cast<const unsigned long long*>(Wsm + k * DDIM + c0);
            const unsigned long long b0 = bp[0], b1 = bp[1],
                                     b2 = bp[2], b3 = bp[3];
            #pragma unroll
            for (int i = 0; i < 4; ++i) {
                const float a = Asm[(r0 + i) * AS_STRIDE + kc + k];
                unsigned long long a2; PACK_AA(a2, a);
                FMA2(acc[i][0], a2, b0, acc[i][0]);
                FMA2(acc[i][1], a2, b1, acc[i][1]);
                FMA2(acc[i][2], a2, b2, acc[i][2]);
                FMA2(acc[i][3], a2, b3, acc[i][3]);
            }
        }
        __syncthreads();
    }

    // ReLU -> hidden smem (aliases Asm; last sync above makes that safe)
    #pragma unroll
    for (int i = 0; i < 4; ++i) {
        #pragma unroll
        for (int j = 0; j < 4; ++j) {
            float lo, hi; UNPACK2(lo, hi, acc[i][j]);
            Hsm[(r0 + i) * HS_STRIDE + c0 + 2 * j]     = fmaxf(lo, 0.0f);
            Hsm[(r0 + i) * HS_STRIDE + c0 + 2 * j + 1] = fmaxf(hi, 0.0f);
        }
    }
    {
        const unsigned long long* bb =
            reinterpret_cast<const unsigned long long*>(be2 + c0);
        const unsigned long long b0 = bb[0], b1 = bb[1], b2 = bb[2], b3 = bb[3];
        #pragma unroll
        for (int i = 0; i < 4; ++i) {
            acc[i][0] = b0; acc[i][1] = b1; acc[i][2] = b2; acc[i][3] = b3;
        }
    }
    __syncthreads();

    // ---- GEMM2: K = 128, chunks of 64 ----
    for (int kc = 0; kc < 128; kc += 64) {
        for (int i = tid; i < 64 * DDIM / 4; i += 256)
            reinterpret_cast<float4*>(Wsm)[i] =
                reinterpret_cast<const float4*>(We2 + (size_t)kc * DDIM)[i];
        __syncthreads();
        #pragma unroll 16
        for (int k = 0; k < 64; ++k) {
            const unsigned long long* bp =
                reinterpret_cast<const unsigned long long*>(Wsm + k * DDIM + c0);
            const unsigned long long b0 = bp[0], b1 = bp[1],
                                     b2 = bp[2], b3 = bp[3];
            #pragma unroll
            for (int i = 0; i < 4; ++i) {
                const float a = Hsm[(r0 + i) * HS_STRIDE + kc + k];
                unsigned long long a2; PACK_AA(a2, a);
                FMA2(acc[i][0], a2, b0, acc[i][0]);
                FMA2(acc[i][1], a2, b1, acc[i][1]);
                FMA2(acc[i][2], a2, b2, acc[i][2]);
                FMA2(acc[i][3], a2, b3, acc[i][3]);
            }
        }
        __syncthreads();
    }

    // Epilogue: write edge_out + scatter-add into g_agg
    #pragma unroll
    for (int i = 0; i < 4; ++i) {
        const int el = r0 + i;
        const int e  = e_base + el;
        float v[8];
        #pragma unroll
        for (int j = 0; j < 4; ++j) UNPACK2(v[2 * j], v[2 * j + 1], acc[i][j]);
        float4* op = reinterpret_cast<float4*>(edge_out + (size_t)e * DDIM + c0);
        op[0] = make_float4(v[0], v[1], v[2], v[3]);
        op[1] = make_float4(v[4], v[5], v[6], v[7]);
        float* ap = g_agg + (size_t)srow[el] * DDIM + c0;
        #pragma unroll
        for (int j = 0; j < 8; ++j) atomicAdd(ap + j, v[j]);
    }
    if (tid < 64) atomicAdd(&g_cnt[srow[tid]], 1.0f);
}

// ---------------------------------------------------------------------------
// Node kernel: per CTA, 64 nodes x 128 outputs.
//   A = [x[n] | agg[n]/max(cnt,1)]  ([64][260])
//   x_out = relu(A @ Wn1 + bn1) @ Wn2 + bn2
// ---------------------------------------------------------------------------
__global__ __launch_bounds__(256, 1)
void node_kernel(const float* __restrict__ x,
                 const float* __restrict__ Wn1,
                 const float* __restrict__ bn1,
                 const float* __restrict__ Wn2,
                 const float* __restrict__ bn2,
                 float* __restrict__ x_out)
{
    extern __shared__ float sm[];
    float* Asm = sm;                          // [64][NS_STRIDE]
    float* Wsm = sm + 64 * NS_STRIDE;         // [64][128]
    float* Hsm = sm;

    const int tid    = threadIdx.x;
    const int n_base = blockIdx.x * 64;

    // Load A: 128 (node,segment) rows; one warp per row.
    {
        const int warp = tid >> 5, lane = tid & 31;
        for (int rr = warp; rr < 128; rr += 8) {
            const int nl  = rr & 63;
            const int seg = rr >> 6;
            const int n   = n_base + nl;
            float4 v = make_float4(0.f, 0.f, 0.f, 0.f);
            if (n < N_NODES) {
                if (seg == 0) {
                    v = reinterpret_cast<const float4*>(x + (size_t)n * DDIM)[lane];
                } else {
                    v = reinterpret_cast<const float4*>(g_agg + (size_t)n * DDIM)[lane];
                    const float inv = 1.0f / fmaxf(g_cnt[n], 1.0f);
                    v.x *= inv; v.y *= inv; v.z *= inv; v.w *= inv;
                }
            }
            reinterpret_cast<float4*>(&Asm[nl * NS_STRIDE + seg * DDIM])[lane] = v;
        }
    }
    __syncthreads();

    const int tx = tid & 15, ty = tid >> 4;
    const int c0 = tx * 8;
    const int r0 = ty * 4;

    unsigned long long acc[4][4];
    {
        const unsigned long long* bb =
            reinterpret_cast<const unsigned long long*>(bn1 + c0);
        const unsigned long long b0 = bb[0], b1 = bb[1], b2 = bb[2], b3 = bb[3];
        #pragma unroll
        for (int i = 0; i < 4; ++i) {
            acc[i][0] = b0; acc[i][1] = b1; acc[i][2] = b2; acc[i][3] = b3;
        }
    }

    // ---- GEMM1: K = 256 ----
    for (int kc = 0; kc < 256; kc += 64) {
        for (int i = tid; i < 64 * DDIM / 4; i += 256)
            reinterpret_cast<float4*>(Wsm)[i] =
                reinterpret_cast<const float4*>(Wn1 + (size_t)kc * DDIM)[i];
        __syncthreads();
        #pragma unroll 16
        for (int k = 0; k < 64; ++k) {
            const unsigned long long* bp =
                reinterpret_cast<const unsigned long long*>(Wsm + k * DDIM + c0);
            const unsigned long long b0 = bp[0], b1 = bp[1],
                                     b2 = bp[2], b3 = bp[3];
            #pragma unroll
            for (int i = 0; i < 4; ++i) {
                const float a = Asm[(r0 + i) * NS_STRIDE + kc + k];
                unsigned long long a2; PACK_AA(a2, a);
                FMA2(acc[i][0], a2, b0, acc[i][0]);
                FMA2(acc[i][1], a2, b1, acc[i][1]);
                FMA2(acc[i][2], a2, b2, acc[i][2]);
                FMA2(acc[i][3], a2, b3, acc[i][3]);
            }
        }
        __syncthreads();
    }

    #pragma unroll
    for (int i = 0; i < 4; ++i) {
        #pragma unroll
        for (int j = 0; j < 4; ++j) {
            float lo, hi; UNPACK2(lo, hi, acc[i][j]);
            Hsm[(r0 + i) * HS_STRIDE + c0 + 2 * j]     = fmaxf(lo, 0.0f);
            Hsm[(r0 + i) * HS_STRIDE + c0 + 2 * j + 1] = fmaxf(hi, 0.0f);
        }
    }
    {
        const unsigned long long* bb =
            reinterpret_cast<const unsigned long long*>(bn2 + c0);
        const unsigned long long b0 = bb[0], b1 = bb[1], b2 = bb[2], b3 = bb[3];
        #pragma unroll
        for (int i = 0; i < 4; ++i) {
            acc[i][0] = b0; acc[i][1] = b1; acc[i][2] = b2; acc[i][3] = b3;
        }
    }
    __syncthreads();

    // ---- GEMM2: K = 128 ----
    for (int kc = 0; kc < 128; kc += 64) {
        for (int i = tid; i < 64 * DDIM / 4; i += 256)
            reinterpret_cast<float4*>(Wsm)[i] =
                reinterpret_cast<const float4*>(Wn2 + (size_t)kc * DDIM)[i];
        __syncthreads();
        #pragma unroll 16
        for (int k = 0; k < 64; ++k) {
            const unsigned long long* bp =
                reinterpret_cast<const unsigned long long*>(Wsm + k * DDIM + c0);
            const unsigned long long b0 = bp[0], b1 = bp[1],
                                     b2 = bp[2], b3 = bp[3];
            #pragma unroll
            for (int i = 0; i < 4; ++i) {
                const float a = Hsm[(r0 + i) * HS_STRIDE + kc + k];
                unsigned long long a2; PACK_AA(a2, a);
                FMA2(acc[i][0], a2, b0, acc[i][0]);
                FMA2(acc[i][1], a2, b1, acc[i][1]);
                FMA2(acc[i][2], a2, b2, acc[i][2]);
                FMA2(acc[i][3], a2, b3, acc[i][3]);
            }
        }
        __syncthreads();
    }

    #pragma unroll
    for (int i = 0; i < 4; ++i) {
        const int n = n_base + r0 + i;
        if (n >= N_NODES) continue;
        float v[8];
        #pragma unroll
        for (int j = 0; j < 4; ++j) UNPACK2(v[2 * j], v[2 * j + 1], acc[i][j]);
        float4* op = reinterpret_cast<float4*>(x_out + (size_t)n * DDIM + c0);
        op[0] = make_float4(v[0], v[1], v[2], v[3]);
        op[1] = make_float4(v[4], v[5], v[6], v[7]);
    }
}

extern "C" void kernel_launch(void* const* d_in, const int* in_sizes, int n_in,
                              void* d_out, int out_size)
{
    const float* x   = (const float*)d_in[0];
    const int*   ei  = (const int*)d_in[1];     // int32: jax x64 is disabled
    const float* ea  = (const float*)d_in[2];
    const float* We1 = (const float*)d_in[3];
    const float* be1 = (const float*)d_in[4];
    const float* We2 = (const float*)d_in[5];
    const float* be2 = (const float*)d_in[6];
    const float* Wn1 = (const float*)d_in[7];
    const float* bn1 = (const float*)d_in[8];
    const float* Wn2 = (const float*)d_in[9];
    const float* bn2 = (const float*)d_in[10];

    float* out      = (float*)d_out;
    float* x_out    = out;                             // (x_out, edge_out) tuple order
    float* edge_out = out + (size_t)N_NODES * DDIM;

    cudaFuncSetAttribute(edge_kernel,
                         cudaFuncAttributeMaxDynamicSharedMemorySize, SMEM_EDGE);
    cudaFuncSetAttribute(node_kernel,
                         cudaFuncAttributeMaxDynamicSharedMemorySize, SMEM_NODE);

    zero_kernel<<<512, 256>>>();
    edge_kernel<<<N_EDGES / 64, 256, SMEM_EDGE>>>(x, ei, ea, We1, be1, We2, be2,
                                                  edge_out);
    node_kernel<<<(N_NODES + 63) / 64, 256, SMEM_NODE>>>(x, Wn1, bn1, Wn2, bn2,
                                                         x_out);
}

// round 5
// speedup vs baseline: 1.5504x; 1.5504x over previous
#include <cuda_runtime.h>
#include <cstdint>
#include <cstddef>

#define N_NODES 50000
#define N_EDGES 640000
#define DDIM 128

#define AS_STRIDE 388   // edge A tile row stride (floats): 384 + 4
#define NS_STRIDE 260   // node A tile: 256 + 4
#define HS_STRIDE 132   // hidden tile: 128 + 4
#define WCHUNK    8192  // 64 k-rows x 128 cols floats = 32KB

static const int SMEM_EDGE = 64 * AS_STRIDE * 4 + 2 * WCHUNK * 4;  // 164864 B
static const int SMEM_NODE = 64 * NS_STRIDE * 4 + 2 * WCHUNK * 4;  // 132096 B

// Scratch (no runtime allocation allowed)
__device__ float g_agg[(size_t)N_NODES * DDIM];
__device__ float g_cnt[N_NODES];

// Packed fp32 pipe: 2 exact fp32 FMAs per instruction
#define FMA2(d, a, b, c) \
    asm("fma.rn.f32x2 %0, %1, %2, %3;" : "=l"(d) : "l"(a), "l"(b), "l"(c))
#define PACK_AA(d, a) \
    asm("mov.b64 %0, {%1, %1};" : "=l"(d) : "f"(a))
#define UNPACK2(lo, hi, v) \
    asm("mov.b64 {%0, %1}, %2;" : "=f"(lo), "=f"(hi) : "l"(v))

__device__ __forceinline__ void cp16(uint32_t dst, const void* src) {
    asm volatile("cp.async.cg.shared.global [%0], [%1], 16;" :: "r"(dst), "l"(src));
}
__device__ __forceinline__ void cp_commit() {
    asm volatile("cp.async.commit_group;");
}
__device__ __forceinline__ void cp_wait1() {
    asm volatile("cp.async.wait_group 1;" ::: "memory");
}
__device__ __forceinline__ void cp_wait0() {
    asm volatile("cp.async.wait_group 0;" ::: "memory");
}
__device__ __forceinline__ uint32_t smem_u32(const void* p) {
    uint32_t r;
    asm("{ .reg .u64 t; cvta.to.shared.u64 t, %1; cvt.u32.u64 %0, t; }"
        : "=r"(r) : "l"(p));
    return r;
}
__device__ __forceinline__ void red_add_v4(float* p, float a, float b, float c,
                                           float d) {
    asm volatile("red.global.add.v4.f32 [%0], {%1, %2, %3, %4};"
                 :: "l"(p), "f"(a), "f"(b), "f"(c), "f"(d) : "memory");
}
__device__ __forceinline__ int clamp_node(int v) {
    return v < 0 ? 0 : (v >= N_NODES ? N_NODES - 1 : v);
}

__global__ void zero_kernel() {
    const size_t stride = (size_t)gridDim.x * blockDim.x;
    for (size_t i = (size_t)blockIdx.x * blockDim.x + threadIdx.x;
         i < (size_t)N_NODES * DDIM; i += stride)
        g_agg[i] = 0.0f;
    for (int i = blockIdx.x * blockDim.x + threadIdx.x; i < N_NODES;
         i += (int)stride)
        g_cnt[i] = 0.0f;
}

// Shared compute core: one 64-k weight chunk against the 64-row A tile.
// Thread (tx,ty) owns rows r0..r0+3 and cols {4tx..4tx+3, 4tx+64..4tx+67}.
// B reads are LDS.128 over 16 contiguous lanes -> conflict-free.
__device__ __forceinline__ void chunk_fma(const float* __restrict__ As,
                                          int astride,
                                          const float* __restrict__ W,
                                          int r0, int tx,
                                          unsigned long long acc[4][2][2]) {
    #pragma unroll 4
    for (int kk = 0; kk < 64; kk += 4) {
        float4 a4[4];
        #pragma unroll
        for (int i = 0; i < 4; ++i)
            a4[i] = *reinterpret_cast<const float4*>(As + (r0 + i) * astride + kk);
        #pragma unroll
        for (int dk = 0; dk < 4; ++dk) {
            const ulonglong2 bg0 = *reinterpret_cast<const ulonglong2*>(
                W + (kk + dk) * DDIM + 4 * tx);
            const ulonglong2 bg1 = *reinterpret_cast<const ulonglong2*>(
                W + (kk + dk) * DDIM + 4 * tx + 64);
            #pragma unroll
            for (int i = 0; i < 4; ++i) {
                const float a = reinterpret_cast<const float*>(&a4[i])[dk];
                unsigned long long a2; PACK_AA(a2, a);
                FMA2(acc[i][0][0], a2, bg0.x, acc[i][0][0]);
                FMA2(acc[i][0][1], a2, bg0.y, acc[i][0][1]);
                FMA2(acc[i][1][0], a2, bg1.x, acc[i][1][0]);
                FMA2(acc[i][1][1], a2, bg1.y, acc[i][1][1]);
            }
        }
    }
}

__device__ __forceinline__ void load_bias(const float* __restrict__ bias,
                                          int tx,
                                          unsigned long long acc[4][2][2]) {
    const ulonglong2 b0 = *reinterpret_cast<const ulonglong2*>(bias + 4 * tx);
    const ulonglong2 b1 = *reinterpret_cast<const ulonglong2*>(bias + 4 * tx + 64);
    #pragma unroll
    for (int i = 0; i < 4; ++i) {
        acc[i][0][0] = b0.x; acc[i][0][1] = b0.y;
        acc[i][1][0] = b1.x; acc[i][1][1] = b1.y;
    }
}

// ---------------------------------------------------------------------------
// Edge kernel: 64 edges x 128 outputs per CTA; 8 weight chunks pipelined
// (6 of We1, 2 of We2), cp.async double-buffered.
// ---------------------------------------------------------------------------
__global__ __launch_bounds__(256, 1)
void edge_kernel(const float* __restrict__ x,
                 const int* __restrict__ ei,
                 const float* __restrict__ ea,
                 const float* __restrict__ We1,
                 const float* __restrict__ be1,
                 const float* __restrict__ We2,
                 const float* __restrict__ be2,
                 float* __restrict__ edge_out)
{
    extern __shared__ float sm[];
    float* Asm = sm;                           // [64][AS_STRIDE]
    float* Hsm = sm;                           // aliases Asm after relu
    float* Wbuf0 = sm + 64 * AS_STRIDE;
    float* Wbuf1 = Wbuf0 + WCHUNK;

    __shared__ int srow[64];
    __shared__ int scol[64];

    const int tid    = threadIdx.x;
    const int e_base = blockIdx.x * 64;
    const uint32_t wb_u32[2] = { smem_u32(Wbuf0), smem_u32(Wbuf1) };

    if (tid < 64) {
        srow[tid] = clamp_node(ei[e_base + tid]);
        scol[tid] = clamp_node(ei[N_EDGES + e_base + tid]);
    }

    // Prefetch weight chunk 0 while gathering A.
    {
        const float4* src = reinterpret_cast<const float4*>(We1);
        for (int t = tid; t < WCHUNK / 4; t += 256)
            cp16(wb_u32[0] + t * 16, src + t);
        cp_commit();
    }
    __syncthreads();

    // Gather A: 192 (edge,segment) rows of 128 floats; one warp per row.
    {
        const int warp = tid >> 5, lane = tid & 31;
        for (int rr = warp; rr < 192; rr += 8) {
            const int e   = rr & 63;
            const int seg = rr >> 6;
            const float* src;
            if (seg == 0)      src = x  + (size_t)srow[e] * DDIM;
            else if (seg == 1) src = x  + (size_t)scol[e] * DDIM;
            else               src = ea + (size_t)(e_base + e) * DDIM;
            const float4 v = reinterpret_cast<const float4*>(src)[lane];
            reinterpret_cast<float4*>(&Asm[e * AS_STRIDE + seg * DDIM])[lane] = v;
        }
    }

    const int tx = tid & 15, ty = tid >> 4;
    const int r0 = ty * 4;

    unsigned long long acc[4][2][2];
    load_bias(be1, tx, acc);

    // 8 chunks: 0..5 = We1 (GEMM1, K=384), 6..7 = We2 (GEMM2, K=128)
    for (int c = 0; c < 8; ++c) {
        if (c + 1 < 8) {
            const float* wsrc = (c + 1 < 6) ? (We1 + (size_t)(c + 1) * WCHUNK)
                                            : (We2 + (size_t)(c + 1 - 6) * WCHUNK);
            const float4* src = reinterpret_cast<const float4*>(wsrc);
            const uint32_t dst = wb_u32[(c + 1) & 1];
            for (int t = tid; t < WCHUNK / 4; t += 256)
                cp16(dst + t * 16, src + t);
            cp_commit();
            cp_wait1();
        } else {
            cp_wait0();
        }
        __syncthreads();

        const float* W  = (c & 1) ? Wbuf1 : Wbuf0;
        const float* As = (c < 6) ? (Asm + c * 64) : (Hsm + (c - 6) * 64);
        const int astr  = (c < 6) ? AS_STRIDE : HS_STRIDE;
        chunk_fma(As, astr, W, r0, tx, acc);

        if (c == 5) {
            __syncthreads();   // all GEMM1 reads of Asm done before Hsm overwrite
            #pragma unroll
            for (int i = 0; i < 4; ++i) {
                #pragma unroll
                for (int g = 0; g < 2; ++g) {
                    float4 h;
                    UNPACK2(h.x, h.y, acc[i][g][0]);
                    UNPACK2(h.z, h.w, acc[i][g][1]);
                    h.x = fmaxf(h.x, 0.f); h.y = fmaxf(h.y, 0.f);
                    h.z = fmaxf(h.z, 0.f); h.w = fmaxf(h.w, 0.f);
                    *reinterpret_cast<float4*>(
                        Hsm + (r0 + i) * HS_STRIDE + 4 * tx + 64 * g) = h;
                }
            }
            load_bias(be2, tx, acc);
        }
        __syncthreads();
    }

    // Epilogue: write edge_out + vector scatter-add into g_agg
    #pragma unroll
    for (int i = 0; i < 4; ++i) {
        const int el = r0 + i;
        const int e  = e_base + el;
        #pragma unroll
        for (int g = 0; g < 2; ++g) {
            float v0, v1, v2, v3;
            UNPACK2(v0, v1, acc[i][g][0]);
            UNPACK2(v2, v3, acc[i][g][1]);
            *reinterpret_cast<float4*>(edge_out + (size_t)e * DDIM + 4 * tx +
                                       64 * g) = make_float4(v0, v1, v2, v3);
            red_add_v4(g_agg + (size_t)srow[el] * DDIM + 4 * tx + 64 * g,
                       v0, v1, v2, v3);
        }
    }
    if (tid < 64) atomicAdd(&g_cnt[srow[tid]], 1.0f);
}

// ---------------------------------------------------------------------------
// Node kernel: 64 nodes x 128 outputs per CTA; 6 chunks (4x Wn1, 2x Wn2).
// ---------------------------------------------------------------------------
__global__ __launch_bounds__(256, 1)
void node_kernel(const float* __restrict__ x,
                 const float* __restrict__ Wn1,
                 const float* __restrict__ bn1,
                 const float* __restrict__ Wn2,
                 const float* __restrict__ bn2,
                 float* __restrict__ x_out)
{
    extern __shared__ float sm[];
    float* Asm = sm;                           // [64][NS_STRIDE]
    float* Hsm = sm;
    float* Wbuf0 = sm + 64 * NS_STRIDE;
    float* Wbuf1 = Wbuf0 + WCHUNK;

    const int tid    = threadIdx.x;
    const int n_base = blockIdx.x * 64;
    const uint32_t wb_u32[2] = { smem_u32(Wbuf0), smem_u32(Wbuf1) };

    {
        const float4* src = reinterpret_cast<const float4*>(Wn1);
        for (int t = tid; t < WCHUNK / 4; t += 256)
            cp16(wb_u32[0] + t * 16, src + t);
        cp_commit();
    }

    // Gather A: 128 (node,segment) rows; one warp per row.
    {
        const int warp = tid >> 5, lane = tid & 31;
        for (int rr = warp; rr < 128; rr += 8) {
            const int nl  = rr & 63;
            const int seg = rr >> 6;
            const int n   = n_base + nl;
            float4 v = make_float4(0.f, 0.f, 0.f, 0.f);
            if (n < N_NODES) {
                if (seg == 0) {
                    v = reinterpret_cast<const float4*>(x + (size_t)n * DDIM)[lane];
                } else {
                    v = reinterpret_cast<const float4*>(g_agg + (size_t)n * DDIM)[lane];
                    const float inv = 1.0f / fmaxf(g_cnt[n], 1.0f);
                    v.x *= inv; v.y *= inv; v.z *= inv; v.w *= inv;
                }
            }
            reinterpret_cast<float4*>(&Asm[nl * NS_STRIDE + seg * DDIM])[lane] = v;
        }
    }

    const int tx = tid & 15, ty = tid >> 4;
    const int r0 = ty * 4;

    unsigned long long acc[4][2][2];
    load_bias(bn1, tx, acc);

    // 6 chunks: 0..3 = Wn1 (K=256), 4..5 = Wn2 (K=128)
    for (int c = 0; c < 6; ++c) {
        if (c + 1 < 6) {
            const float* wsrc = (c + 1 < 4) ? (Wn1 + (size_t)(c + 1) * WCHUNK)
                                            : (Wn2 + (size_t)(c + 1 - 4) * WCHUNK);
            const float4* src = reinterpret_cast<const float4*>(wsrc);
            const uint32_t dst = wb_u32[(c + 1) & 1];
            for (int t = tid; t < WCHUNK / 4; t += 256)
                cp16(dst + t * 16, src + t);
            cp_commit();
            cp_wait1();
        } else {
            cp_wait0();
        }
        __syncthreads();

        const float* W  = (c & 1) ? Wbuf1 : Wbuf0;
        const float* As = (c < 4) ? (Asm + c * 64) : (Hsm + (c - 4) * 64);
        const int astr  = (c < 4) ? NS_STRIDE : HS_STRIDE;
        chunk_fma(As, astr, W, r0, tx, acc);

        if (c == 3) {
            __syncthreads();
            #pragma unroll
            for (int i = 0; i < 4; ++i) {
                #pragma unroll
                for (int g = 0; g < 2; ++g) {
                    float4 h;
                    UNPACK2(h.x, h.y, acc[i][g][0]);
                    UNPACK2(h.z, h.w, acc[i][g][1]);
                    h.x = fmaxf(h.x, 0.f); h.y = fmaxf(h.y, 0.f);
                    h.z = fmaxf(h.z, 0.f); h.w = fmaxf(h.w, 0.f);
                    *reinterpret_cast<float4*>(
                        Hsm + (r0 + i) * HS_STRIDE + 4 * tx + 64 * g) = h;
                }
            }
            load_bias(bn2, tx, acc);
        }
        __syncthreads();
    }

    #pragma unroll
    for (int i = 0; i < 4; ++i) {
        const int n = n_base + r0 + i;
        if (n >= N_NODES) continue;
        #pragma unroll
        for (int g = 0; g < 2; ++g) {
            float v0, v1, v2, v3;
            UNPACK2(v0, v1, acc[i][g][0]);
            UNPACK2(v2, v3, acc[i][g][1]);
            *reinterpret_cast<float4*>(x_out + (size_t)n * DDIM + 4 * tx +
                                       64 * g) = make_float4(v0, v1, v2, v3);
        }
    }
}

extern "C" void kernel_launch(void* const* d_in, const int* in_sizes, int n_in,
                              void* d_out, int out_size)
{
    const float* x   = (const float*)d_in[0];
    const int*   ei  = (const int*)d_in[1];     // int32: jax x64 disabled
    const float* ea  = (const float*)d_in[2];
    const float* We1 = (const float*)d_in[3];
    const float* be1 = (const float*)d_in[4];
    const float* We2 = (const float*)d_in[5];
    const float* be2 = (const float*)d_in[6];
    const float* Wn1 = (const float*)d_in[7];
    const float* bn1 = (const float*)d_in[8];
    const float* Wn2 = (const float*)d_in[9];
    const float* bn2 = (const float*)d_in[10];

    float* out      = (float*)d_out;
    float* x_out    = out;                             // (x_out, edge_out)
    float* edge_out = out + (size_t)N_NODES * DDIM;

    cudaFuncSetAttribute(edge_kernel,
                         cudaFuncAttributeMaxDynamicSharedMemorySize, SMEM_EDGE);
    cudaFuncSetAttribute(node_kernel,
                         cudaFuncAttributeMaxDynamicSharedMemorySize, SMEM_NODE);

    zero_kernel<<<512, 256>>>();
    edge_kernel<<<N_EDGES / 64, 256, SMEM_EDGE>>>(x, ei, ea, We1, be1, We2, be2,
                                                  edge_out);
    node_kernel<<<(N_NODES + 63) / 64, 256, SMEM_NODE>>>(x, Wn1, bn1, Wn2, bn2,
                                                         x_out);
}